// round 16
// baseline (speedup 1.0000x reference)
#include <cuda_runtime.h>
#include <math.h>

#define D    2048
#define E    64
#define NT   16384      // B*S tokens
#define KC   32         // k-chunk
#define TTOK 32         // tokens per gemm block  -> grid 512
#define SB   128        // tokens per router block
#define NSB  (NT / SB)  // 128 router blocks
#define WPAD 34         // padded row: 34 ull = 272B (16B-aligned, bank-staggered)

typedef unsigned long long ull;

// ---------------- device scratch (no allocations allowed) ----------------
__device__ float g_logits[(size_t)NT * E];   // 4 MB
__device__ float g_P[NSB * E];
__device__ float g_C[NSB * E];
__device__ float g_Z[NSB];

// ---------------- f32x2 helpers ------------------------------------------
__device__ __forceinline__ ull pack2(float lo, float hi) {
    ull r;
    asm("mov.b64 %0, {%1, %2};" : "=l"(r) : "r"(__float_as_uint(lo)), "r"(__float_as_uint(hi)));
    return r;
}
__device__ __forceinline__ void unpack2(ull v, float& lo, float& hi) {
    unsigned int a, b;
    asm("mov.b64 {%0, %1}, %2;" : "=r"(a), "=r"(b) : "l"(v));
    lo = __uint_as_float(a); hi = __uint_as_float(b);
}
__device__ __forceinline__ void fma2(ull& d, ull a, ull b) {
    asm("fma.rn.f32x2 %0, %1, %2, %0;" : "+l"(d) : "l"(a), "l"(b));
}

// ---------------- GEMM: logits[t][e] = sum_d x[t][d] * gw[e][d] ----------
// Block: 32 tokens x 64 experts, 256 threads, grid 512 (3.46 CTAs/SM).
// Thread: 2 tokens x 4 experts (2 f32x2 pairs). Operands pre-paired in smem:
//   xsd[k][t]  = (x,x)      -> A via LDS.64, no packing MOV in inner loop
//   wsp[k][ep] = (w0,w1)    -> B via LDS.128 (2 pairs), no MOV
__global__ void __launch_bounds__(256) gemm_kernel(const float* __restrict__ x,
                                                   const float* __restrict__ gw) {
    __shared__ ull xsd[KC][WPAD];   // only [0..TTOK) used per row
    __shared__ ull wsp[KC][WPAD];   // only [0..E/2) used per row

    const int tid = threadIdx.x;
    const int t0  = blockIdx.x * TTOK;
    const int tg  = tid >> 4;            // 0..15 -> tokens 2tg, 2tg+1
    const int eg  = tid & 15;            // 0..15 -> expert pairs 2eg, 2eg+1 (experts 4eg..4eg+3)

    // x loader: token xr (0..31), k-quad xc (0..7): 1 x LDG.128 per chunk
    const int xr = tid >> 3;
    const int xc = tid & 7;
    // w loader: expert wr (0..63), k-octet wc2 (0..3): 2 x LDG.128 per chunk
    const int wr  = tid >> 2;
    const int wc2 = tid & 3;

    const float* xp = x  + (size_t)(t0 + xr) * D + xc * 4;
    const float* wp = gw + (size_t)wr        * D + wc2 * 8;

    ull acc[2][2];
    acc[0][0] = acc[0][1] = acc[1][0] = acc[1][1] = 0ULL;   // (0.f, 0.f)

    // prefetch chunk 0
    float4 xa, wa0, wa1;
    xa  = *(const float4*)(xp);
    wa0 = *(const float4*)(wp);
    wa1 = *(const float4*)(wp + 4);

    for (int kc = 0; kc < D; kc += KC) {
        __syncthreads();   // previous chunk's readers done
        // store x as duplicated pairs: xsd[k][t] = (v, v)
        xsd[xc * 4 + 0][xr] = pack2(xa.x, xa.x);
        xsd[xc * 4 + 1][xr] = pack2(xa.y, xa.y);
        xsd[xc * 4 + 2][xr] = pack2(xa.z, xa.z);
        xsd[xc * 4 + 3][xr] = pack2(xa.w, xa.w);
        // store w transposed into pair slots: wsp[k][wr/2] halves
        {
            float wv[8] = {wa0.x, wa0.y, wa0.z, wa0.w, wa1.x, wa1.y, wa1.z, wa1.w};
#pragma unroll
            for (int j = 0; j < 8; j++) {
                ((float*)&wsp[wc2 * 8 + j][wr >> 1])[wr & 1] = wv[j];
            }
        }
        __syncthreads();
        // prefetch next chunk (overlaps with compute below)
        if (kc + KC < D) {
            xa  = *(const float4*)(xp + kc + KC);
            wa0 = *(const float4*)(wp + kc + KC);
            wa1 = *(const float4*)(wp + kc + KC + 4);
        }
        // compute: per k, 3 LDS + 4 FFMA2 (fma pipe sees only FFMA2)
#pragma unroll
        for (int kk = 0; kk < KC; kk++) {
            ull a0 = xsd[kk][2 * tg];
            ull a1 = xsd[kk][2 * tg + 1];
            ulonglong2 bv = *(const ulonglong2*)&wsp[kk][2 * eg];
            fma2(acc[0][0], a0, bv.x); fma2(acc[0][1], a0, bv.y);
            fma2(acc[1][0], a1, bv.x); fma2(acc[1][1], a1, bv.y);
        }
    }

    // epilogue: token t0+2tg+i, experts 4eg..4eg+3
#pragma unroll
    for (int i = 0; i < 2; i++) {
        float r0, r1, r2, r3;
        unpack2(acc[i][0], r0, r1);
        unpack2(acc[i][1], r2, r3);
        *(float4*)&g_logits[(size_t)(t0 + 2 * tg + i) * E + 4 * eg] =
            make_float4(r0, r1, r2, r3);
    }
}

// ---------------- Router: softmax + top2 + partial aux -------------------
__global__ void __launch_bounds__(256) router_kernel(float* __restrict__ out) {
    __shared__ float sP[8][64];
    __shared__ int   sC[8][64];
    __shared__ float sZ[8];

    const int tid  = threadIdx.x;
    const int w    = tid >> 5;
    const int lane = tid & 31;

    sC[w][lane] = 0; sC[w][lane + 32] = 0;
    if (lane == 0) sZ[w] = 0.f;
    __syncwarp();

    float p0 = 0.f, p1 = 0.f, zacc = 0.f;
    const int tokBase = blockIdx.x * SB + w * 16;

    for (int it = 0; it < 16; it++) {
        const int tok = tokBase + it;
        const float* lrow = &g_logits[(size_t)tok * E];
        float l0 = lrow[lane];
        float l1 = lrow[lane + 32];

        float m = fmaxf(l0, l1);
#pragma unroll
        for (int o = 16; o > 0; o >>= 1) m = fmaxf(m, __shfl_xor_sync(0xffffffffu, m, o));

        float e0 = expf(l0 - m), e1 = expf(l1 - m);
        float s = e0 + e1;
#pragma unroll
        for (int o = 16; o > 0; o >>= 1) s += __shfl_xor_sync(0xffffffffu, s, o);

        float inv = 1.f / s;
        p0 += e0 * inv;
        p1 += e1 * inv;

        float lse = logf(s) + m;
        zacc += lse * lse;

        // top-1 candidate per lane (tie -> lower index, matching jax top_k)
        float bv; int bi;
        if (e1 > e0) { bv = e1; bi = lane + 32; } else { bv = e0; bi = lane; }
#pragma unroll
        for (int o = 16; o > 0; o >>= 1) {
            float ov = __shfl_xor_sync(0xffffffffu, bv, o);
            int   oi = __shfl_xor_sync(0xffffffffu, bi, o);
            if (ov > bv || (ov == bv && oi < bi)) { bv = ov; bi = oi; }
        }
        // top-2: exclude bi
        float b2; int b2i;
        if (bi == lane)            { b2 = e1; b2i = lane + 32; }
        else if (bi == lane + 32)  { b2 = e0; b2i = lane; }
        else if (e1 > e0)          { b2 = e1; b2i = lane + 32; }
        else                       { b2 = e0; b2i = lane; }
#pragma unroll
        for (int o = 16; o > 0; o >>= 1) {
            float ov = __shfl_xor_sync(0xffffffffu, b2, o);
            int   oi = __shfl_xor_sync(0xffffffffu, b2i, o);
            if (ov > b2 || (ov == b2 && oi < b2i)) { b2 = ov; b2i = oi; }
        }

        if (lane == 0) {
            float sw = bv + b2;
            out[tok * 2 + 0]           = (float)bi;
            out[tok * 2 + 1]           = (float)b2i;
            out[2 * NT + tok * 2 + 0]  = bv / sw;
            out[2 * NT + tok * 2 + 1]  = b2 / sw;
            sC[w][bi]++;
            sC[w][b2i]++;
        }
    }

    sP[w][lane] = p0;
    sP[w][lane + 32] = p1;
    if (lane == 0) sZ[w] = zacc;
    __syncthreads();

    if (tid < 64) {
        float ps = 0.f, cs = 0.f;
#pragma unroll
        for (int ww = 0; ww < 8; ww++) {
            ps += sP[ww][tid];
            cs += (float)sC[ww][tid];
        }
        g_P[blockIdx.x * E + tid] = ps;
        g_C[blockIdx.x * E + tid] = cs;
    }
    if (tid == 64) {
        float z = 0.f;
#pragma unroll
        for (int ww = 0; ww < 8; ww++) z += sZ[ww];
        g_Z[blockIdx.x] = z;
    }
}

// ---------------- Finalize aux loss --------------------------------------
__global__ void __launch_bounds__(64) finalize_kernel(float* __restrict__ out) {
    __shared__ float red[64];
    const int tid = threadIdx.x;   // 64 threads, one per expert
    float P = 0.f, C = 0.f;
    for (int b = 0; b < NSB; b++) {
        P += g_P[b * E + tid];
        C += g_C[b * E + tid];
    }
    float f  = C / (float)(NT * 2);
    float Pm = P / (float)NT;
    red[tid] = f * Pm;
    __syncthreads();
    for (int o = 32; o > 0; o >>= 1) {
        if (tid < o) red[tid] += red[tid + o];
        __syncthreads();
    }
    if (tid == 0) {
        float z = 0.f;
        for (int b = 0; b < NSB; b++) z += g_Z[b];
        float balance = (float)E * red[0];
        float zmean   = z / (float)NT;
        out[4 * NT] = 0.01f * balance + 0.001f * zmean;
    }
}

// ---------------- launch --------------------------------------------------
extern "C" void kernel_launch(void* const* d_in, const int* in_sizes, int n_in,
                              void* d_out, int out_size) {
    const float* x  = (const float*)d_in[0];
    const float* gw = (const float*)d_in[1];
    float* out = (float*)d_out;

    gemm_kernel<<<NT / TTOK, 256>>>(x, gw);
    router_kernel<<<NT / SB, 256>>>(out);
    finalize_kernel<<<1, 64>>>(out);
}